// round 4
// baseline (speedup 1.0000x reference)
#include <cuda_runtime.h>
#include <math.h>

#define H_DIM 1024
#define R_DIM 32
#define NAG 256
#define BTOK 8192
#define NTH 512
#define NW 16
#define SB 64             // tokens per super-batch (inter capacity)
#define SUB 16            // tokens per h-staging sub-batch
#define LN_EPS 1e-5f
#define ALPHA_MAX 5.0f

// Global scratch
__device__ int g_cnt[NAG];            // zero-initialized; main kernel self-resets
__device__ int g_toks[NAG][BTOK];

__global__ void build_lists_kernel(const int* __restrict__ ids) {
    int i = blockIdx.x * blockDim.x + threadIdx.x;
    if (i < BTOK) {
        int a = ids[i] & (NAG - 1);
        int p = atomicAdd(&g_cnt[a], 1);
        g_toks[a][p] = i;
    }
}

// SMEM layout (floats):
//  buf    [32768]          U or V                      offset 0
//  hstage [SUB*1024=16384]                             offset 32768
//  inter  [2][SB][32] = 4096                           offset 49152
//  ssq    [NW][4][2] = 128                             offset 53248
//  stoks  [SB] ints                                    offset 53376
#define OFF_H     32768
#define OFF_INTER 49152
#define OFF_SSQ   53248
#define OFF_TOK   53376
#define SMEM_BYTES (53376 * 4 + SB * 4)

__global__ __launch_bounds__(NTH, 1)
void div_inject_kernel(const float* __restrict__ h,
                       const float* __restrict__ log_alpha,
                       const float* __restrict__ gamma,
                       const float* __restrict__ beta,
                       const float* __restrict__ pu,
                       const float* __restrict__ pv,
                       float*       __restrict__ out)
{
    extern __shared__ float smem[];
    float* buf    = smem;
    float* hstage = smem + OFF_H;
    float* inter  = smem + OFF_INTER;
    float* ssq    = smem + OFF_SSQ;
    int*   stoks  = (int*)(smem + OFF_TOK);
    __shared__ int s_total;

    const int tid  = threadIdx.x;
    const int lane = tid & 31;
    const int wid  = tid >> 5;
    const int agent = blockIdx.x;

    if (tid == 0) { s_total = g_cnt[agent]; g_cnt[agent] = 0; }
    __syncthreads();
    const int total = s_total;
    if (total == 0) return;
    const int* toks = g_toks[agent];

    const float alpha = fminf(expf(log_alpha[0]), ALPHA_MAX);

    for (int base = 0; base < total; base += SB) {
        const int nb2 = min(SB, total - base);

        // stage token ids
        if (tid < nb2) stoks[tid] = toks[base + tid];

        // ---- load U[agent] (H x R, 128 KB) ----
        {
            const float4* src = (const float4*)(pu + (size_t)agent * (H_DIM * R_DIM));
            float4* dst = (float4*)buf;
            #pragma unroll
            for (int i = 0; i < (H_DIM * R_DIM) / 4 / NTH; ++i)
                dst[tid + i * NTH] = src[tid + i * NTH];
        }
        __syncthreads();

        // ---- phase A over sub-batches: stage h, compute partial inter ----
        const int nsub = (nb2 + SUB - 1) / SUB;
        const int tp = wid >> 1;       // token pair 0..7
        const int kh = wid & 1;        // k-half 0/1

        for (int sub = 0; sub < nsub; ++sub) {
            const int sbase = sub * SUB;
            const int scount = min(SUB, nb2 - sbase);

            // stage h rows (coalesced LDG.128 -> STS.128)
            for (int j = tid; j < scount * (H_DIM / 4); j += NTH) {
                const int lt = j >> 8;
                const int c  = j & 255;
                ((float4*)hstage)[lt * (H_DIM / 4) + c] =
                    ((const float4*)(h + (size_t)stoks[sbase + lt] * H_DIM))[c];
            }
            __syncthreads();

            // compute: warp = 2 tokens x 512 k
            const int lt0 = min(tp * 2,     scount - 1);
            const int lt1 = min(tp * 2 + 1, scount - 1);
            const float4* hp0 = (const float4*)(hstage + lt0 * H_DIM) + kh * 128;
            const float4* hp1 = (const float4*)(hstage + lt1 * H_DIM) + kh * 128;
            const float* ub = buf + kh * 512 * R_DIM + lane;

            float a0x=0.f,a0y=0.f,a0z=0.f,a0w=0.f;
            float a1x=0.f,a1y=0.f,a1z=0.f,a1w=0.f;

            #pragma unroll 8
            for (int k4 = 0; k4 < 128; ++k4) {
                float4 x0 = hp0[k4];
                float4 x1 = hp1[k4];
                const float* up = ub + k4 * 4 * R_DIM;
                float u0 = up[0];
                float u1 = up[R_DIM];
                float u2 = up[2 * R_DIM];
                float u3 = up[3 * R_DIM];
                a0x = fmaf(x0.x, u0, a0x); a0y = fmaf(x0.y, u1, a0y);
                a0z = fmaf(x0.z, u2, a0z); a0w = fmaf(x0.w, u3, a0w);
                a1x = fmaf(x1.x, u0, a1x); a1y = fmaf(x1.y, u1, a1y);
                a1z = fmaf(x1.z, u2, a1z); a1w = fmaf(x1.w, u3, a1w);
            }
            inter[kh * (SB * R_DIM) + (sbase + lt0) * R_DIM + lane] = a0x + a0y + a0z + a0w;
            inter[kh * (SB * R_DIM) + (sbase + lt1) * R_DIM + lane] = a1x + a1y + a1z + a1w;
            __syncthreads();
        }

        // ---- load V[agent] (R x H, 128 KB) over U ----
        {
            const float4* src = (const float4*)(pv + (size_t)agent * (R_DIM * H_DIM));
            float4* dst = (float4*)buf;
            #pragma unroll
            for (int i = 0; i < (R_DIM * H_DIM) / 4 / NTH; ++i)
                dst[tid + i * NTH] = src[tid + i * NTH];
        }
        __syncthreads();

        // ---- phase B: warp-pair = 4 tokens, each warp owns a 512-col half ----
        const int pair = wid >> 1;     // 0..7 -> tokens
        const int jh   = wid & 1;      // column half
        const int nsweep = (nb2 + 31) / 32;

        for (int sw = 0; sw < nsweep; ++sw) {
            const int tb = sw * 32 + pair * 4;
            int lt[4];
            #pragma unroll
            for (int i = 0; i < 4; ++i) lt[i] = min(tb + i, nb2 - 1);

            float iv[4];
            #pragma unroll
            for (int i = 0; i < 4; ++i)
                iv[i] = inter[lt[i] * R_DIM + lane] + inter[SB * R_DIM + lt[i] * R_DIM + lane];

            float4 acc[4][4];
            #pragma unroll
            for (int i = 0; i < 4; ++i)
                #pragma unroll
                for (int m = 0; m < 4; ++m) acc[i][m] = make_float4(0.f,0.f,0.f,0.f);

            #pragma unroll 4
            for (int r = 0; r < R_DIM; ++r) {
                const float4* vr = (const float4*)(buf + r * H_DIM + jh * 512) + lane;
                float4 vv0 = vr[0];
                float4 vv1 = vr[32];
                float4 vv2 = vr[64];
                float4 vv3 = vr[96];
                #pragma unroll
                for (int i = 0; i < 4; ++i) {
                    const float b = __shfl_sync(0xffffffffu, iv[i], r);
                    acc[i][0].x = fmaf(b, vv0.x, acc[i][0].x);
                    acc[i][0].y = fmaf(b, vv0.y, acc[i][0].y);
                    acc[i][0].z = fmaf(b, vv0.z, acc[i][0].z);
                    acc[i][0].w = fmaf(b, vv0.w, acc[i][0].w);
                    acc[i][1].x = fmaf(b, vv1.x, acc[i][1].x);
                    acc[i][1].y = fmaf(b, vv1.y, acc[i][1].y);
                    acc[i][1].z = fmaf(b, vv1.z, acc[i][1].z);
                    acc[i][1].w = fmaf(b, vv1.w, acc[i][1].w);
                    acc[i][2].x = fmaf(b, vv2.x, acc[i][2].x);
                    acc[i][2].y = fmaf(b, vv2.y, acc[i][2].y);
                    acc[i][2].z = fmaf(b, vv2.z, acc[i][2].z);
                    acc[i][2].w = fmaf(b, vv2.w, acc[i][2].w);
                    acc[i][3].x = fmaf(b, vv3.x, acc[i][3].x);
                    acc[i][3].y = fmaf(b, vv3.y, acc[i][3].y);
                    acc[i][3].z = fmaf(b, vv3.z, acc[i][3].z);
                    acc[i][3].w = fmaf(b, vv3.w, acc[i][3].w);
                }
            }

            // residual + own-half sums
            #pragma unroll
            for (int i = 0; i < 4; ++i) {
                const int t = stoks[lt[i]];
                const float4* hq = (const float4*)(h + (size_t)t * H_DIM) + jh * 128 + lane;
                float s = 0.f, sq = 0.f;
                #pragma unroll
                for (int m = 0; m < 4; ++m) {
                    float4 hv = hq[m * 32];
                    float4 d;
                    d.x = fmaf(alpha, acc[i][m].x, hv.x);
                    d.y = fmaf(alpha, acc[i][m].y, hv.y);
                    d.z = fmaf(alpha, acc[i][m].z, hv.z);
                    d.w = fmaf(alpha, acc[i][m].w, hv.w);
                    acc[i][m] = d;
                    s  += d.x + d.y + d.z + d.w;
                    sq += d.x*d.x + d.y*d.y + d.z*d.z + d.w*d.w;
                }
                #pragma unroll
                for (int o = 16; o > 0; o >>= 1) {
                    s  += __shfl_xor_sync(0xffffffffu, s,  o);
                    sq += __shfl_xor_sync(0xffffffffu, sq, o);
                }
                if (lane == 0) {
                    ssq[wid * 8 + i * 2 + 0] = s;
                    ssq[wid * 8 + i * 2 + 1] = sq;
                }
            }
            __syncthreads();

            // combine with partner warp, normalize, store
            #pragma unroll
            for (int i = 0; i < 4; ++i) {
                const float s  = ssq[wid * 8 + i * 2 + 0] + ssq[(wid ^ 1) * 8 + i * 2 + 0];
                const float sq = ssq[wid * 8 + i * 2 + 1] + ssq[(wid ^ 1) * 8 + i * 2 + 1];
                const float mean = s * (1.0f / H_DIM);
                const float var  = sq * (1.0f / H_DIM) - mean * mean;
                const float rstd = rsqrtf(var + LN_EPS);

                const int t = stoks[lt[i]];
                float4* op = (float4*)(out + (size_t)t * H_DIM) + jh * 128 + lane;
                const float4* g4 = (const float4*)gamma + jh * 128 + lane;
                const float4* b4 = (const float4*)beta  + jh * 128 + lane;
                #pragma unroll
                for (int m = 0; m < 4; ++m) {
                    float4 g = g4[m * 32];
                    float4 bb = b4[m * 32];
                    float4 d = acc[i][m];
                    float4 o_;
                    o_.x = (d.x - mean) * rstd * g.x + bb.x;
                    o_.y = (d.y - mean) * rstd * g.y + bb.y;
                    o_.z = (d.z - mean) * rstd * g.z + bb.z;
                    o_.w = (d.w - mean) * rstd * g.w + bb.w;
                    op[m * 32] = o_;
                }
            }
            __syncthreads();
        }
    }
}

extern "C" void kernel_launch(void* const* d_in, const int* in_sizes, int n_in,
                              void* d_out, int out_size)
{
    const float* h     = (const float*)d_in[0];
    const float* la    = (const float*)d_in[1];
    const float* gamma = (const float*)d_in[2];
    const float* beta  = (const float*)d_in[3];
    const float* pu    = (const float*)d_in[4];
    const float* pv    = (const float*)d_in[5];
    const int*   ids   = (const int*)d_in[6];
    float*       out   = (float*)d_out;

    build_lists_kernel<<<(BTOK + 255) / 256, 256>>>(ids);

    cudaFuncSetAttribute(div_inject_kernel,
                         cudaFuncAttributeMaxDynamicSharedMemorySize, SMEM_BYTES);
    div_inject_kernel<<<NAG, NTH, SMEM_BYTES>>>(h, la, gamma, beta, pu, pv, out);
}

// round 8
// speedup vs baseline: 1.1127x; 1.1127x over previous
#include <cuda_runtime.h>
#include <math.h>

#define H_DIM 1024
#define R_DIM 32
#define NAG 256
#define BTOK 8192
#define NTH 256
#define NW 8
#define SB 16
#define LN_EPS 1e-5f
#define ALPHA_MAX 5.0f

// ---- global scratch (allowed: __device__ statics) ----
__device__ int g_cnt[NAG];              // zero at module load; main kernel self-resets
__device__ int g_toks[NAG][BTOK];

__global__ void build_lists_kernel(const int* __restrict__ ids) {
    int i = blockIdx.x * blockDim.x + threadIdx.x;
    if (i < BTOK) {
        int a = ids[i] & (NAG - 1);
        int p = atomicAdd(&g_cnt[a], 1);
        g_toks[a][p] = i;
    }
}

// ---- cp.async helpers ----
__device__ __forceinline__ void cp16(void* s, const void* g) {
    unsigned sa = (unsigned)__cvta_generic_to_shared(s);
    asm volatile("cp.async.cg.shared.global [%0], [%1], 16;\n" :: "r"(sa), "l"(g));
}
#define CP_COMMIT() asm volatile("cp.async.commit_group;\n" ::: "memory")
#define CP_WAIT0()  asm volatile("cp.async.wait_group 0;\n" ::: "memory")

// SMEM layout (floats):
//   ubuf   [8192]   32 KB  (U quarter, then V quarter)     @ 0
//   hstage [16384]  64 KB  (SB rows x 1024; h then d)      @ 8192
//   gb     [2048]    8 KB  (gamma | beta)                  @ 24576
//   stoks  [16] int                                        @ 26624
#define OFF_HS  8192
#define OFF_GB  24576
#define OFF_TOK 26624
#define SMEM_BYTES ((26624 + 16) * 4)

__global__ __launch_bounds__(NTH, 2)
void div_inject_kernel(const float* __restrict__ h,
                       const float* __restrict__ log_alpha,
                       const float* __restrict__ gamma,
                       const float* __restrict__ beta,
                       const float* __restrict__ pu,
                       const float* __restrict__ pv,
                       float*       __restrict__ out)
{
    extern __shared__ float smem[];
    float* ubuf   = smem;
    float* hstage = smem + OFF_HS;
    float* gb     = smem + OFF_GB;
    int*   stoks  = (int*)(smem + OFF_TOK);
    __shared__ int s_total;

    const int tid   = threadIdx.x;
    const int lane  = tid & 31;
    const int wid   = tid >> 5;
    const int agent = blockIdx.x;

    if (tid == 0) { s_total = g_cnt[agent]; g_cnt[agent] = 0; }

    // stage gamma/beta (512 float4) via cp.async
    {
        float4* dst = (float4*)gb;
        cp16(dst + tid,       (const float4*)gamma + tid);
        cp16(dst + 256 + tid, (const float4*)beta  + tid);
        CP_COMMIT();
    }
    __syncthreads();
    const int total = s_total;
    if (total == 0) { CP_WAIT0(); return; }

    const float alpha = fminf(expf(log_alpha[0]), ALPHA_MAX);
    const int* toks = g_toks[agent];

    for (int base = 0; base < total; base += SB) {
        const int nb = min(SB, total - base);

        if (tid < SB) stoks[tid] = toks[base + min(tid, nb - 1)];

        // ---- stage h rows for this batch (SB x 1024 floats) ----
        {
            #pragma unroll
            for (int it = 0; it < (SB * 256) / NTH; ++it) {
                const int i   = tid + it * NTH;
                const int row = i >> 8;
                const int col = i & 255;
                const int t   = toks[base + min(row, nb - 1)];
                cp16((float4*)hstage + i, (const float4*)h + (size_t)t * 256 + col);
            }
            CP_COMMIT();
        }

        // ownership: warp wid owns tokens 2wid, 2wid+1 (only if < nb)
        const bool v0 = (2 * wid)     < nb;
        const bool v1 = (2 * wid + 1) < nb;
        const int lt0 = min(2 * wid,     nb - 1);   // clamped for reads only
        const int lt1 = min(2 * wid + 1, nb - 1);

        // ---- phase A: inter[t][lane] over 4 U-quarters, acc in regs ----
        float a0x = 0.f, a0y = 0.f, a0z = 0.f, a0w = 0.f;
        float a1x = 0.f, a1y = 0.f, a1z = 0.f, a1w = 0.f;

        #pragma unroll 1
        for (int kq = 0; kq < 4; ++kq) {
            const float4* usrc = (const float4*)pu + (size_t)agent * 8192 + kq * 2048;
            #pragma unroll
            for (int i = 0; i < 8; ++i)
                cp16((float4*)ubuf + tid + i * NTH, usrc + tid + i * NTH);
            CP_COMMIT(); CP_WAIT0();
            __syncthreads();

            const float4* hp0 = (const float4*)hstage + lt0 * 256 + kq * 64;
            const float4* hp1 = (const float4*)hstage + lt1 * 256 + kq * 64;
            const float*  ub  = ubuf + lane;

            #pragma unroll 8
            for (int k4 = 0; k4 < 64; ++k4) {
                float4 x0 = hp0[k4];
                float4 x1 = hp1[k4];
                const float* up = ub + k4 * 128;
                float u0 = up[0];
                float u1 = up[32];
                float u2 = up[64];
                float u3 = up[96];
                a0x = fmaf(x0.x, u0, a0x); a0y = fmaf(x0.y, u1, a0y);
                a0z = fmaf(x0.z, u2, a0z); a0w = fmaf(x0.w, u3, a0w);
                a1x = fmaf(x1.x, u0, a1x); a1y = fmaf(x1.y, u1, a1y);
                a1z = fmaf(x1.z, u2, a1z); a1w = fmaf(x1.w, u3, a1w);
            }
            __syncthreads();
        }
        const float iv0 = (a0x + a0y) + (a0z + a0w);
        const float iv1 = (a1x + a1y) + (a1z + a1w);

        // ---- phase B: pert over 4 V-quarters; residual into hstage (owners only) ----
        float s0 = 0.f, sq0 = 0.f, s1 = 0.f, sq1 = 0.f;

        #pragma unroll 1
        for (int jq = 0; jq < 4; ++jq) {
            const float4* vsrc = (const float4*)pv + (size_t)agent * 8192;
            #pragma unroll
            for (int i = 0; i < 8; ++i) {
                const int idx = tid + i * NTH;      // 0..2047
                const int r   = idx >> 6;
                const int c   = idx & 63;
                cp16((float4*)ubuf + idx, vsrc + r * 256 + jq * 64 + c);
            }
            CP_COMMIT(); CP_WAIT0();
            __syncthreads();

            float4 p00 = make_float4(0.f,0.f,0.f,0.f);
            float4 p01 = make_float4(0.f,0.f,0.f,0.f);
            float4 p10 = make_float4(0.f,0.f,0.f,0.f);
            float4 p11 = make_float4(0.f,0.f,0.f,0.f);

            const float4* vb = (const float4*)ubuf;
            #pragma unroll 4
            for (int r = 0; r < 32; ++r) {
                const float b0 = __shfl_sync(0xffffffffu, iv0, r);
                const float b1 = __shfl_sync(0xffffffffu, iv1, r);
                float4 vx0 = vb[r * 64 + lane];
                float4 vx1 = vb[r * 64 + 32 + lane];
                p00.x = fmaf(b0, vx0.x, p00.x); p00.y = fmaf(b0, vx0.y, p00.y);
                p00.z = fmaf(b0, vx0.z, p00.z); p00.w = fmaf(b0, vx0.w, p00.w);
                p01.x = fmaf(b0, vx1.x, p01.x); p01.y = fmaf(b0, vx1.y, p01.y);
                p01.z = fmaf(b0, vx1.z, p01.z); p01.w = fmaf(b0, vx1.w, p01.w);
                p10.x = fmaf(b1, vx0.x, p10.x); p10.y = fmaf(b1, vx0.y, p10.y);
                p10.z = fmaf(b1, vx0.z, p10.z); p10.w = fmaf(b1, vx0.w, p10.w);
                p11.x = fmaf(b1, vx1.x, p11.x); p11.y = fmaf(b1, vx1.y, p11.y);
                p11.z = fmaf(b1, vx1.z, p11.z); p11.w = fmaf(b1, vx1.w, p11.w);
            }

            // residual: d = h + alpha*p; ONLY the owning warp writes its row
            if (v0) {
                float4* hs0 = (float4*)hstage + lt0 * 256 + jq * 64;
                float4 ha = hs0[lane], hb = hs0[32 + lane];
                float4 d0, d1;
                d0.x = fmaf(alpha, p00.x, ha.x); d0.y = fmaf(alpha, p00.y, ha.y);
                d0.z = fmaf(alpha, p00.z, ha.z); d0.w = fmaf(alpha, p00.w, ha.w);
                d1.x = fmaf(alpha, p01.x, hb.x); d1.y = fmaf(alpha, p01.y, hb.y);
                d1.z = fmaf(alpha, p01.z, hb.z); d1.w = fmaf(alpha, p01.w, hb.w);
                hs0[lane] = d0; hs0[32 + lane] = d1;
                s0  += (d0.x + d0.y) + (d0.z + d0.w) + (d1.x + d1.y) + (d1.z + d1.w);
                sq0 += d0.x*d0.x + d0.y*d0.y + d0.z*d0.z + d0.w*d0.w
                     + d1.x*d1.x + d1.y*d1.y + d1.z*d1.z + d1.w*d1.w;
            }
            if (v1) {
                float4* hs1 = (float4*)hstage + lt1 * 256 + jq * 64;
                float4 ha = hs1[lane], hb = hs1[32 + lane];
                float4 d0, d1;
                d0.x = fmaf(alpha, p10.x, ha.x); d0.y = fmaf(alpha, p10.y, ha.y);
                d0.z = fmaf(alpha, p10.z, ha.z); d0.w = fmaf(alpha, p10.w, ha.w);
                d1.x = fmaf(alpha, p11.x, hb.x); d1.y = fmaf(alpha, p11.y, hb.y);
                d1.z = fmaf(alpha, p11.z, hb.z); d1.w = fmaf(alpha, p11.w, hb.w);
                hs1[lane] = d0; hs1[32 + lane] = d1;
                s1  += (d0.x + d0.y) + (d0.z + d0.w) + (d1.x + d1.y) + (d1.z + d1.w);
                sq1 += d0.x*d0.x + d0.y*d0.y + d0.z*d0.z + d0.w*d0.w
                     + d1.x*d1.x + d1.y*d1.y + d1.z*d1.z + d1.w*d1.w;
            }
            __syncthreads();
        }

        // ---- LayerNorm finalize (warp-local per token; owners only store) ----
        #pragma unroll
        for (int o = 16; o > 0; o >>= 1) {
            s0  += __shfl_xor_sync(0xffffffffu, s0,  o);
            sq0 += __shfl_xor_sync(0xffffffffu, sq0, o);
            s1  += __shfl_xor_sync(0xffffffffu, s1,  o);
            sq1 += __shfl_xor_sync(0xffffffffu, sq1, o);
        }
        const float4* gs = (const float4*)gb;

        if (v0) {
            const float mean0 = s0 * (1.0f / H_DIM);
            const float var0  = sq0 * (1.0f / H_DIM) - mean0 * mean0;
            const float rstd0 = rsqrtf(var0 + LN_EPS);
            const int t0 = stoks[lt0];
            float4* o0 = (float4*)out + (size_t)t0 * 256;
            const float4* ds = (const float4*)hstage + lt0 * 256;
            #pragma unroll
            for (int m = 0; m < 8; ++m) {
                float4 d = ds[m * 32 + lane];
                float4 g = gs[m * 32 + lane];
                float4 bb = gs[256 + m * 32 + lane];
                float4 o_;
                o_.x = (d.x - mean0) * rstd0 * g.x + bb.x;
                o_.y = (d.y - mean0) * rstd0 * g.y + bb.y;
                o_.z = (d.z - mean0) * rstd0 * g.z + bb.z;
                o_.w = (d.w - mean0) * rstd0 * g.w + bb.w;
                o0[m * 32 + lane] = o_;
            }
        }
        if (v1) {
            const float mean1 = s1 * (1.0f / H_DIM);
            const float var1  = sq1 * (1.0f / H_DIM) - mean1 * mean1;
            const float rstd1 = rsqrtf(var1 + LN_EPS);
            const int t1 = stoks[lt1];
            float4* o1 = (float4*)out + (size_t)t1 * 256;
            const float4* ds = (const float4*)hstage + lt1 * 256;
            #pragma unroll
            for (int m = 0; m < 8; ++m) {
                float4 d = ds[m * 32 + lane];
                float4 g = gs[m * 32 + lane];
                float4 bb = gs[256 + m * 32 + lane];
                float4 o_;
                o_.x = (d.x - mean1) * rstd1 * g.x + bb.x;
                o_.y = (d.y - mean1) * rstd1 * g.y + bb.y;
                o_.z = (d.z - mean1) * rstd1 * g.z + bb.z;
                o_.w = (d.w - mean1) * rstd1 * g.w + bb.w;
                o1[m * 32 + lane] = o_;
            }
        }
        __syncthreads();   // hstage/stoks reuse safety for next batch
    }
}

extern "C" void kernel_launch(void* const* d_in, const int* in_sizes, int n_in,
                              void* d_out, int out_size)
{
    const float* h     = (const float*)d_in[0];
    const float* la    = (const float*)d_in[1];
    const float* gamma = (const float*)d_in[2];
    const float* beta  = (const float*)d_in[3];
    const float* pu    = (const float*)d_in[4];
    const float* pv    = (const float*)d_in[5];
    const int*   ids   = (const int*)d_in[6];
    float*       out   = (float*)d_out;

    build_lists_kernel<<<(BTOK + 255) / 256, 256>>>(ids);

    cudaFuncSetAttribute(div_inject_kernel,
                         cudaFuncAttributeMaxDynamicSharedMemorySize, SMEM_BYTES);
    div_inject_kernel<<<NAG, NTH, SMEM_BYTES>>>(h, la, gamma, beta, pu, pv, out);
}